// round 12
// baseline (speedup 1.0000x reference)
#include <cuda_runtime.h>
#include <cuda_bf16.h>
#include <cstdint>

// x: [32,2048] int32 ids in [0,100000); W: [256,100000] f32 (EMBED-major);
// b: [256] f32; out: [65536,256] f32 = W[:, x[t]] + b.
//
// K1 hist_rank+scan : rank[t]=atomicAdd(bins[id>>5],1); the LAST-finishing
//                     CTA (ticket) scans the 3125 bins -> offs, zeroes bins.
// K2 scatter        : atomic-free sorted[offs[bin]+rank[t]] = {id, t}
// K3 gather         : 32 sorted tokens x 128 dims per CTA; coalesced strided
//                     LDG -> STS.128 tile (stride 132) -> LDS.128 + bias ->
//                     STG.128 evict-first contiguous rows.
static constexpr int VOCAB = 100000;
static constexpr int EMBED = 256;
static constexpr int NTOK  = 32 * 2048;            // 65536
static constexpr int NBINS = (VOCAB + 31) / 32;    // 3125
static constexpr int HDIM  = 128;
static constexpr int TSTR  = 132;
static constexpr int HCTAS = 128;                  // hist/scatter CTAs
static constexpr int BPT   = 13;                   // bins per scan thread (256*13>=3125)

__device__ int      g_bins[NBINS];   // zero at load; scan re-zeroes each launch
__device__ int      g_offs[NBINS];
__device__ int      g_rank[NTOK];
__device__ int2     g_sorted[NTOK];
__device__ unsigned g_ticket;        // zero at load; scan CTA re-zeroes

__device__ __forceinline__ int clamp_id(int v) {
    return min(max(v, 0), VOCAB - 1);
}

// ---- K1: histogram + rank; last CTA performs the scan --------------------
__global__ __launch_bounds__(256) void hist_scan_kernel(const int* __restrict__ x)
{
    __shared__ int  warp_tot[8];
    __shared__ bool s_last;

    const int tid = threadIdx.x;
    const int t0  = (blockIdx.x * 256 + tid) * 2;

    const int2 xv = *reinterpret_cast<const int2*>(x + t0);
    const int v0 = clamp_id(xv.x), v1 = clamp_id(xv.y);
    int2 r;
    r.x = atomicAdd(&g_bins[v0 >> 5], 1);
    r.y = atomicAdd(&g_bins[v1 >> 5], 1);
    *reinterpret_cast<int2*>(g_rank + t0) = r;

    // ticket: last CTA to arrive does the scan
    __threadfence();
    __syncthreads();
    if (tid == 0)
        s_last = (atomicAdd(&g_ticket, 1) == HCTAS - 1);
    __syncthreads();
    if (!s_last) return;

    // ---- scan (one CTA, 256 threads, 13 bins each) ----------------------
    const int lane = tid & 31;
    const int wid  = tid >> 5;

    int c[BPT]; int s = 0;
#pragma unroll
    for (int k = 0; k < BPT; ++k) {
        int idx = tid * BPT + k;
        c[k] = (idx < NBINS) ? __ldcg(&g_bins[idx]) : 0;
        if (idx < NBINS) __stcg(&g_bins[idx], 0);  // restore invariant
        s += c[k];
    }
    int incl = s;
#pragma unroll
    for (int off = 1; off < 32; off <<= 1) {
        int t = __shfl_up_sync(0xffffffff, incl, off);
        if (lane >= off) incl += t;
    }
    if (lane == 31) warp_tot[wid] = incl;
    __syncthreads();
    if (wid == 0 && lane < 8) {                    // scan 8 warp totals
        int wv = warp_tot[lane];
        int wi = wv;
#pragma unroll
        for (int off = 1; off < 8; off <<= 1) {
            int t = __shfl_up_sync(0x000000ff, wi, off);
            if (lane >= off) wi += t;
        }
        warp_tot[lane] = wi - wv;                  // exclusive base per warp
    }
    __syncthreads();
    int base = warp_tot[wid] + (incl - s);
#pragma unroll
    for (int k = 0; k < BPT; ++k) {
        int idx = tid * BPT + k;
        if (idx < NBINS) __stcg(&g_offs[idx], base);
        base += c[k];
    }
    if (tid == 0) g_ticket = 0;                    // replay invariant
}

// ---- K2: atomic-free scatter, 2 tokens/thread ----------------------------
__global__ __launch_bounds__(256) void scatter_kernel(const int* __restrict__ x)
{
    const int t0 = (blockIdx.x * 256 + threadIdx.x) * 2;
    const int2 xv = *reinterpret_cast<const int2*>(x + t0);
    const int2 rv = *reinterpret_cast<const int2*>(g_rank + t0);
    const int v0 = clamp_id(xv.x), v1 = clamp_id(xv.y);
    const int o0 = __ldcg(&g_offs[v0 >> 5]);       // 2-deep MLP
    const int o1 = __ldcg(&g_offs[v1 >> 5]);
    __stcg(&g_sorted[o0 + rv.x], make_int2(v0, t0));
    __stcg(&g_sorted[o1 + rv.y], make_int2(v1, t0 + 1));
}

// ---- K3: gather, 32 tokens x 128 dims per CTA ----------------------------
__global__ __launch_bounds__(256) void gather_kernel(
    const float* __restrict__ W,
    const float* __restrict__ bias,
    float*       __restrict__ out)
{
    __shared__ __align__(16) float tile[32][TSTR];
    __shared__ int s_id[32], s_tok[32];

    const int tid   = threadIdx.x;
    const int group = blockIdx.x >> 1;
    const int half  = blockIdx.x & 1;
    const int dim0  = half * HDIM;

    if (tid < 32) {
        int2 p = g_sorted[group * 32 + tid];
        s_id[tid]  = p.x;
        s_tok[tid] = p.y;
    }
    __syncthreads();

    const int w = tid >> 5;          // warp -> dims [16w,16w+16) of half
    const int l = tid & 31;          // lane -> sorted token

    const int vid = s_id[l];
    const float* wp = W + (size_t)(dim0 + w * 16) * VOCAB + (size_t)vid;
    float rr[16];
#pragma unroll
    for (int j = 0; j < 16; ++j)
        rr[j] = __ldg(wp + (size_t)j * VOCAB);     // coalesced via sort

#pragma unroll
    for (int j = 0; j < 4; ++j) {
        float4 v4 = make_float4(rr[4*j], rr[4*j+1], rr[4*j+2], rr[4*j+3]);
        *reinterpret_cast<float4*>(&tile[l][w * 16 + 4 * j]) = v4;
    }
    __syncthreads();

    const float4 bv = __ldg(reinterpret_cast<const float4*>(bias) + half * 32 + l);
#pragma unroll
    for (int i = 0; i < 4; ++i) {
        const int t    = w * 4 + i;
        const int orig = s_tok[t];
        float4 v4 = *reinterpret_cast<const float4*>(&tile[t][4 * l]);
        v4.x += bv.x; v4.y += bv.y; v4.z += bv.z; v4.w += bv.w;
        __stcs(reinterpret_cast<float4*>(out + (size_t)orig * EMBED + dim0) + l, v4);
    }
}

extern "C" void kernel_launch(void* const* d_in, const int* in_sizes, int n_in,
                              void* d_out, int out_size)
{
    const int*   x    = (const int*)d_in[0];
    const float* W    = (const float*)d_in[1];
    const float* bias = (const float*)d_in[2];
    float*       out  = (float*)d_out;

    hist_scan_kernel<<<HCTAS, 256>>>(x);           // 128 CTAs, 2 tok/thread
    scatter_kernel<<<HCTAS, 256>>>(x);             // 128 CTAs, 2 tok/thread
    gather_kernel<<<(NTOK / 32) * 2, 256>>>(W, bias, out);
}

// round 13
// speedup vs baseline: 1.2526x; 1.2526x over previous
#include <cuda_runtime.h>
#include <cuda_bf16.h>
#include <cstdint>

// x: [32,2048] int32 ids in [0,100000); W: [256,100000] f32 (EMBED-major);
// b: [256] f32; out: [65536,256] f32 = W[:, x[t]] + b.
//
// 4 kernels chained with Programmatic Dependent Launch (PDL): each dependent
// kernel launches while its producer drains; cudaGridDependencySynchronize()
// guards all reads of producer-written data. Independent loads (x) are issued
// before the sync to hide their latency behind the producer's tail.
//
// K1 hist_rank : rank[t]=atomicAdd(bins[id>>5],1), 4 tok/thread
// K2 scan      : 1 CTA x 1024, shuffle scan of 3125 bins; consume-and-zero
// K3 scatter   : atomic-free sorted[offs[bin]+rank[t]] = {id,t}, 4 tok/thread
// K4 gather    : 32 sorted tokens x 128 dims per CTA; coalesced strided LDG
//                -> STS.128 tile (stride 132) -> LDS.128+bias -> STG.128
//                evict-first contiguous rows.
static constexpr int VOCAB = 100000;
static constexpr int EMBED = 256;
static constexpr int NTOK  = 32 * 2048;            // 65536
static constexpr int NBINS = (VOCAB + 31) / 32;    // 3125
static constexpr int HDIM  = 128;
static constexpr int TSTR  = 132;

__device__ int  g_bins[NBINS];     // zero at load; scan re-zeroes each launch
__device__ int  g_offs[NBINS];
__device__ int  g_rank[NTOK];
__device__ int2 g_sorted[NTOK];

__device__ __forceinline__ int clamp_id(int v) {
    return min(max(v, 0), VOCAB - 1);
}

// ---- K1: histogram + rank, 4 tokens/thread -------------------------------
__global__ __launch_bounds__(256) void hist_rank_kernel(const int* __restrict__ x) {
    const int t0 = (blockIdx.x * 256 + threadIdx.x) * 4;
    const int4 xv = *reinterpret_cast<const int4*>(x + t0);
    const int v0 = clamp_id(xv.x), v1 = clamp_id(xv.y);
    const int v2 = clamp_id(xv.z), v3 = clamp_id(xv.w);
    int4 r;
    r.x = atomicAdd(&g_bins[v0 >> 5], 1);          // 4 independent atomics
    r.y = atomicAdd(&g_bins[v1 >> 5], 1);
    r.z = atomicAdd(&g_bins[v2 >> 5], 1);
    r.w = atomicAdd(&g_bins[v3 >> 5], 1);
    *reinterpret_cast<int4*>(g_rank + t0) = r;
}

// ---- K2: single-CTA shuffle scan (PDL consumer) --------------------------
__global__ __launch_bounds__(1024) void scan_kernel() {
    __shared__ int warp_tot[32];
    const int tid  = threadIdx.x;
    const int lane = tid & 31;
    const int wid  = tid >> 5;

#if __CUDA_ARCH__ >= 900
    cudaGridDependencySynchronize();               // wait for K1's bins
#endif

    int c[4]; int s = 0;
#pragma unroll
    for (int k = 0; k < 4; ++k) {
        int idx = tid * 4 + k;
        c[k] = (idx < NBINS) ? __ldcg(&g_bins[idx]) : 0;
        if (idx < NBINS) __stcg(&g_bins[idx], 0);  // restore invariant
        s += c[k];
    }
    int incl = s;
#pragma unroll
    for (int off = 1; off < 32; off <<= 1) {
        int t = __shfl_up_sync(0xffffffff, incl, off);
        if (lane >= off) incl += t;
    }
    if (lane == 31) warp_tot[wid] = incl;
    __syncthreads();
    if (wid == 0) {
        int wv = warp_tot[lane];
        int wi = wv;
#pragma unroll
        for (int off = 1; off < 32; off <<= 1) {
            int t = __shfl_up_sync(0xffffffff, wi, off);
            if (lane >= off) wi += t;
        }
        warp_tot[lane] = wi - wv;                  // exclusive base per warp
    }
    __syncthreads();
    int base = warp_tot[wid] + (incl - s);
#pragma unroll
    for (int k = 0; k < 4; ++k) {
        int idx = tid * 4 + k;
        if (idx < NBINS) __stcg(&g_offs[idx], base);
        base += c[k];
    }
}

// ---- K3: atomic-free scatter (PDL consumer; x prefetched pre-sync) -------
__global__ __launch_bounds__(256) void scatter_kernel(const int* __restrict__ x) {
    const int t0 = (blockIdx.x * 256 + threadIdx.x) * 4;
    const int4 xv = *reinterpret_cast<const int4*>(x + t0);   // independent: before sync
    const int v[4] = { clamp_id(xv.x), clamp_id(xv.y), clamp_id(xv.z), clamp_id(xv.w) };

#if __CUDA_ARCH__ >= 900
    cudaGridDependencySynchronize();               // wait for rank (K1) + offs (K2)
#endif

    const int4 rv = *reinterpret_cast<const int4*>(g_rank + t0);
    const int rk[4] = { rv.x, rv.y, rv.z, rv.w };
    int of[4];
#pragma unroll
    for (int k = 0; k < 4; ++k) of[k] = __ldcg(&g_offs[v[k] >> 5]);
#pragma unroll
    for (int k = 0; k < 4; ++k)
        __stcg(&g_sorted[of[k] + rk[k]], make_int2(v[k], t0 + k));
}

// ---- K4: gather (PDL consumer), 32 tokens x 128 dims per CTA -------------
__global__ __launch_bounds__(256) void gather_kernel(
    const float* __restrict__ W,
    const float* __restrict__ bias,
    float*       __restrict__ out)
{
    __shared__ __align__(16) float tile[32][TSTR];
    __shared__ int s_id[32], s_tok[32];

    const int tid   = threadIdx.x;
    const int group = blockIdx.x >> 1;
    const int half  = blockIdx.x & 1;
    const int dim0  = half * HDIM;
    const int w = tid >> 5;          // warp -> dims [16w,16w+16) of half
    const int l = tid & 31;          // lane -> sorted token

    // independent: bias load before the dependency sync
    const float4 bv = __ldg(reinterpret_cast<const float4*>(bias) + half * 32 + l);

#if __CUDA_ARCH__ >= 900
    cudaGridDependencySynchronize();               // wait for g_sorted (K3)
#endif

    if (tid < 32) {
        int2 p = g_sorted[group * 32 + tid];
        s_id[tid]  = p.x;
        s_tok[tid] = p.y;
    }
    __syncthreads();

    const int vid = s_id[l];
    const float* wp = W + (size_t)(dim0 + w * 16) * VOCAB + (size_t)vid;
    float rr[16];
#pragma unroll
    for (int j = 0; j < 16; ++j)
        rr[j] = __ldg(wp + (size_t)j * VOCAB);     // coalesced via sort

#pragma unroll
    for (int j = 0; j < 4; ++j) {
        float4 v4 = make_float4(rr[4*j], rr[4*j+1], rr[4*j+2], rr[4*j+3]);
        *reinterpret_cast<float4*>(&tile[l][w * 16 + 4 * j]) = v4;
    }
    __syncthreads();

#pragma unroll
    for (int i = 0; i < 4; ++i) {
        const int t    = w * 4 + i;
        const int orig = s_tok[t];
        float4 v4 = *reinterpret_cast<const float4*>(&tile[t][4 * l]);
        v4.x += bv.x; v4.y += bv.y; v4.z += bv.z; v4.w += bv.w;
        __stcs(reinterpret_cast<float4*>(out + (size_t)orig * EMBED + dim0) + l, v4);
    }
}

// ---- host: PDL-chained launches ------------------------------------------
template <typename K, typename... Args>
static void launch_pdl(K kernel, dim3 grid, dim3 block, Args... args)
{
    cudaLaunchAttribute attr;
    attr.id = cudaLaunchAttributeProgrammaticStreamSerialization;
    attr.val.programmaticStreamSerializationAllowed = 1;
    cudaLaunchConfig_t cfg = {};
    cfg.gridDim  = grid;
    cfg.blockDim = block;
    cfg.attrs    = &attr;
    cfg.numAttrs = 1;
    cfg.stream   = 0;                               // capture stream (legacy default)
    cudaLaunchKernelEx(&cfg, kernel, args...);
}

extern "C" void kernel_launch(void* const* d_in, const int* in_sizes, int n_in,
                              void* d_out, int out_size)
{
    const int*   x    = (const int*)d_in[0];
    const float* W    = (const float*)d_in[1];
    const float* bias = (const float*)d_in[2];
    float*       out  = (float*)d_out;

    hist_rank_kernel<<<NTOK / 1024, 256>>>(x);                 // 64 CTAs
    launch_pdl(scan_kernel,    dim3(1),               dim3(1024));
    launch_pdl(scatter_kernel, dim3(NTOK / 1024),     dim3(256), x);
    launch_pdl(gather_kernel,  dim3((NTOK / 32) * 2), dim3(256), W, bias, out);
}

// round 14
// speedup vs baseline: 1.2608x; 1.0065x over previous
#include <cuda_runtime.h>
#include <cuda_bf16.h>
#include <cstdint>

// x: [32,2048] int32 ids in [0,100000); W: [256,100000] f32 (EMBED-major);
// b: [256] f32; out: [65536,256] f32 = W[:, x[t]] + b.
//
// PDL-chained pipeline + background L2 prefetch of W:
// K1 hist_rank : 64 work CTAs (rank[t]=atomicAdd(bins[id>>5],1), 4 tok/thr)
//                + 800 prefetch CTAs that trigger PDL completion at ENTRY and
//                then stream all of W through L2 (__ldcg, asm sink) in the
//                background while K2-K4 run. DRAM is otherwise idle during
//                the prologue; this moves gather's ~63MB compulsory W re-read
//                into that idle window.
// K2 scan      : 1 CTA x 1024, shuffle scan of 3125 bins; consume-and-zero
// K3 scatter   : atomic-free sorted[offs[bin]+rank[t]] = {id,t}, 4 tok/thr
// K4 gather    : 32 sorted tokens x 128 dims per CTA; coalesced strided LDG
//                (W now L2-hot) -> STS.128 tile -> LDS.128+bias -> STG.128
//                evict-first contiguous rows.
static constexpr int VOCAB = 100000;
static constexpr int EMBED = 256;
static constexpr int NTOK  = 32 * 2048;            // 65536
static constexpr int NBINS = (VOCAB + 31) / 32;    // 3125
static constexpr int HDIM  = 128;
static constexpr int TSTR  = 132;

static constexpr int HCTAS    = NTOK / 1024;       // 64 hist/scatter work CTAs
static constexpr int NF4      = EMBED * VOCAB / 4; // 6,400,000 float4 in W
static constexpr int PF_CTAS  = 800;               // prefetch CTAs
static constexpr int PF_ITER  = 32;                // f4 per thread -> 128KB/CTA

__device__ int  g_bins[NBINS];     // zero at load; scan re-zeroes each launch
__device__ int  g_offs[NBINS];
__device__ int  g_rank[NTOK];
__device__ int2 g_sorted[NTOK];

__device__ __forceinline__ int clamp_id(int v) {
    return min(max(v, 0), VOCAB - 1);
}

// ---- K1: histogram + rank (work CTAs) | W->L2 prefetch (rest) ------------
__global__ __launch_bounds__(256) void hist_prefetch_kernel(
    const int*   __restrict__ x,
    const float* __restrict__ W)
{
    const int tid = threadIdx.x;

    if (blockIdx.x >= HCTAS) {
        // -------- prefetch CTA: release PDL gate immediately, then stream
#if __CUDA_ARCH__ >= 900
        cudaTriggerProgrammaticLaunchCompletion();
#endif
        const int pf = blockIdx.x - HCTAS;
        const float4* w4 = reinterpret_cast<const float4*>(W);
        float acc = 0.0f;
        const int base = pf * (256 * PF_ITER);
#pragma unroll 8
        for (int i = 0; i < PF_ITER; ++i) {
            const int idx = base + i * 256 + tid;
            if (idx < NF4) {
                float4 v = __ldcg(w4 + idx);       // allocate in L2
                acc += v.x + v.y + v.z + v.w;
            }
        }
        asm volatile("" :: "f"(acc));              // keep loads alive
        return;
    }

    // -------- work CTA: histogram + rank, 4 tokens/thread
    const int t0 = (blockIdx.x * 256 + tid) * 4;
    const int4 xv = *reinterpret_cast<const int4*>(x + t0);
    const int v0 = clamp_id(xv.x), v1 = clamp_id(xv.y);
    const int v2 = clamp_id(xv.z), v3 = clamp_id(xv.w);
    int4 r;
    r.x = atomicAdd(&g_bins[v0 >> 5], 1);          // 4 independent atomics
    r.y = atomicAdd(&g_bins[v1 >> 5], 1);
    r.z = atomicAdd(&g_bins[v2 >> 5], 1);
    r.w = atomicAdd(&g_bins[v3 >> 5], 1);
    *reinterpret_cast<int4*>(g_rank + t0) = r;
    // implicit trigger at exit
}

// ---- K2: single-CTA shuffle scan (PDL consumer) --------------------------
__global__ __launch_bounds__(1024) void scan_kernel() {
    __shared__ int warp_tot[32];
    const int tid  = threadIdx.x;
    const int lane = tid & 31;
    const int wid  = tid >> 5;

#if __CUDA_ARCH__ >= 900
    cudaGridDependencySynchronize();               // wait for K1 work CTAs
#endif

    int c[4]; int s = 0;
#pragma unroll
    for (int k = 0; k < 4; ++k) {
        int idx = tid * 4 + k;
        c[k] = (idx < NBINS) ? __ldcg(&g_bins[idx]) : 0;
        if (idx < NBINS) __stcg(&g_bins[idx], 0);  // restore invariant
        s += c[k];
    }
    int incl = s;
#pragma unroll
    for (int off = 1; off < 32; off <<= 1) {
        int t = __shfl_up_sync(0xffffffff, incl, off);
        if (lane >= off) incl += t;
    }
    if (lane == 31) warp_tot[wid] = incl;
    __syncthreads();
    if (wid == 0) {
        int wv = warp_tot[lane];
        int wi = wv;
#pragma unroll
        for (int off = 1; off < 32; off <<= 1) {
            int t = __shfl_up_sync(0xffffffff, wi, off);
            if (lane >= off) wi += t;
        }
        warp_tot[lane] = wi - wv;                  // exclusive base per warp
    }
    __syncthreads();
    int base = warp_tot[wid] + (incl - s);
#pragma unroll
    for (int k = 0; k < 4; ++k) {
        int idx = tid * 4 + k;
        if (idx < NBINS) __stcg(&g_offs[idx], base);
        base += c[k];
    }
}

// ---- K3: atomic-free scatter (PDL consumer; x prefetched pre-sync) -------
__global__ __launch_bounds__(256) void scatter_kernel(const int* __restrict__ x) {
    const int t0 = (blockIdx.x * 256 + threadIdx.x) * 4;
    const int4 xv = *reinterpret_cast<const int4*>(x + t0);   // pre-sync load
    const int v[4] = { clamp_id(xv.x), clamp_id(xv.y), clamp_id(xv.z), clamp_id(xv.w) };

#if __CUDA_ARCH__ >= 900
    cudaGridDependencySynchronize();               // wait for offs (K2)
#endif

    const int4 rv = *reinterpret_cast<const int4*>(g_rank + t0);
    const int rk[4] = { rv.x, rv.y, rv.z, rv.w };
    int of[4];
#pragma unroll
    for (int k = 0; k < 4; ++k) of[k] = __ldcg(&g_offs[v[k] >> 5]);
#pragma unroll
    for (int k = 0; k < 4; ++k)
        __stcg(&g_sorted[of[k] + rk[k]], make_int2(v[k], t0 + k));
}

// ---- K4: gather (PDL consumer), 32 tokens x 128 dims per CTA -------------
__global__ __launch_bounds__(256) void gather_kernel(
    const float* __restrict__ W,
    const float* __restrict__ bias,
    float*       __restrict__ out)
{
    __shared__ __align__(16) float tile[32][TSTR];
    __shared__ int s_id[32], s_tok[32];

    const int tid   = threadIdx.x;
    const int group = blockIdx.x >> 1;
    const int half  = blockIdx.x & 1;
    const int dim0  = half * HDIM;
    const int w = tid >> 5;          // warp -> dims [16w,16w+16) of half
    const int l = tid & 31;          // lane -> sorted token

    // independent: bias load before the dependency sync
    const float4 bv = __ldg(reinterpret_cast<const float4*>(bias) + half * 32 + l);

#if __CUDA_ARCH__ >= 900
    cudaGridDependencySynchronize();               // wait for g_sorted (K3)
#endif

    if (tid < 32) {
        int2 p = g_sorted[group * 32 + tid];
        s_id[tid]  = p.x;
        s_tok[tid] = p.y;
    }
    __syncthreads();

    const int vid = s_id[l];
    const float* wp = W + (size_t)(dim0 + w * 16) * VOCAB + (size_t)vid;
    float rr[16];
#pragma unroll
    for (int j = 0; j < 16; ++j)
        rr[j] = __ldg(wp + (size_t)j * VOCAB);     // coalesced via sort; L2-hot

#pragma unroll
    for (int j = 0; j < 4; ++j) {
        float4 v4 = make_float4(rr[4*j], rr[4*j+1], rr[4*j+2], rr[4*j+3]);
        *reinterpret_cast<float4*>(&tile[l][w * 16 + 4 * j]) = v4;
    }
    __syncthreads();

#pragma unroll
    for (int i = 0; i < 4; ++i) {
        const int t    = w * 4 + i;
        const int orig = s_tok[t];
        float4 v4 = *reinterpret_cast<const float4*>(&tile[t][4 * l]);
        v4.x += bv.x; v4.y += bv.y; v4.z += bv.z; v4.w += bv.w;
        __stcs(reinterpret_cast<float4*>(out + (size_t)orig * EMBED + dim0) + l, v4);
    }
}

// ---- host: PDL-chained launches ------------------------------------------
template <typename K, typename... Args>
static void launch_pdl(K kernel, dim3 grid, dim3 block, Args... args)
{
    cudaLaunchAttribute attr;
    attr.id = cudaLaunchAttributeProgrammaticStreamSerialization;
    attr.val.programmaticStreamSerializationAllowed = 1;
    cudaLaunchConfig_t cfg = {};
    cfg.gridDim  = grid;
    cfg.blockDim = block;
    cfg.attrs    = &attr;
    cfg.numAttrs = 1;
    cfg.stream   = 0;
    cudaLaunchKernelEx(&cfg, kernel, args...);
}

extern "C" void kernel_launch(void* const* d_in, const int* in_sizes, int n_in,
                              void* d_out, int out_size)
{
    const int*   x    = (const int*)d_in[0];
    const float* W    = (const float*)d_in[1];
    const float* bias = (const float*)d_in[2];
    float*       out  = (float*)d_out;

    hist_prefetch_kernel<<<HCTAS + PF_CTAS, 256>>>(x, W);
    launch_pdl(scan_kernel,    dim3(1),               dim3(1024));
    launch_pdl(scatter_kernel, dim3(HCTAS),           dim3(256), x);
    launch_pdl(gather_kernel,  dim3((NTOK / 32) * 2), dim3(256), W, bias, out);
}

// round 15
// speedup vs baseline: 1.2805x; 1.0157x over previous
#include <cuda_runtime.h>
#include <cuda_bf16.h>
#include <cstdint>

// x: [32,2048] int32 ids in [0,100000); W: [256,100000] f32 (EMBED-major);
// b: [256] f32; out: [65536,256] f32 = W[:, x[t]] + b.
//
// 3-kernel PDL chain (one fewer dependent kernel than R13):
// K1 hist_rank    : rank[t]=atomicAdd(bins[id>>5],1), 4 tok/thread, 64 CTAs
// K2 scan_scatter : EVERY CTA redundantly shuffle-scans the 3125 bins into
//                   smem (12.5KB, L2-hot broadcast), then scatters its own
//                   1024 tokens atomic-free: sorted[offs[bin]+rank] = {id,t}.
//                   Deletes the serial scan kernel + one launch boundary.
// K3 gather       : 32 sorted tokens x 128 dims per CTA; first 13 CTAs also
//                   re-zero g_bins (ordered after K2 by PDL). Coalesced
//                   strided LDG -> STS.128 tile (stride 132) -> LDS.128+bias
//                   -> STG.128 evict-first contiguous rows.
static constexpr int VOCAB = 100000;
static constexpr int EMBED = 256;
static constexpr int NTOK  = 32 * 2048;            // 65536
static constexpr int NBINS = (VOCAB + 31) / 32;    // 3125
static constexpr int HDIM  = 128;
static constexpr int TSTR  = 132;
static constexpr int HCTAS = NTOK / 1024;          // 64 work CTAs (4 tok/thr)
static constexpr int BPT   = 13;                   // bins per thread (256*13>=3125)

__device__ int  g_bins[NBINS];     // zero at load; gather re-zeroes each launch
__device__ int  g_rank[NTOK];
__device__ int2 g_sorted[NTOK];

__device__ __forceinline__ int clamp_id(int v) {
    return min(max(v, 0), VOCAB - 1);
}

// ---- K1: histogram + rank, 4 tokens/thread -------------------------------
__global__ __launch_bounds__(256) void hist_rank_kernel(const int* __restrict__ x) {
    const int t0 = (blockIdx.x * 256 + threadIdx.x) * 4;
    const int4 xv = *reinterpret_cast<const int4*>(x + t0);
    const int v0 = clamp_id(xv.x), v1 = clamp_id(xv.y);
    const int v2 = clamp_id(xv.z), v3 = clamp_id(xv.w);
    int4 r;
    r.x = atomicAdd(&g_bins[v0 >> 5], 1);          // 4 independent atomics
    r.y = atomicAdd(&g_bins[v1 >> 5], 1);
    r.z = atomicAdd(&g_bins[v2 >> 5], 1);
    r.w = atomicAdd(&g_bins[v3 >> 5], 1);
    *reinterpret_cast<int4*>(g_rank + t0) = r;
}

// ---- K2: redundant per-CTA scan + scatter (PDL consumer) -----------------
__global__ __launch_bounds__(256) void scan_scatter_kernel(const int* __restrict__ x)
{
    __shared__ int s_offs[NBINS];                  // 12.5 KB
    __shared__ int warp_tot[8];

    const int tid  = threadIdx.x;
    const int lane = tid & 31;
    const int wid  = tid >> 5;
    const int t0   = (blockIdx.x * 256 + tid) * 4;

    // independent input load before the dependency sync
    const int4 xv = *reinterpret_cast<const int4*>(x + t0);
    const int v[4] = { clamp_id(xv.x), clamp_id(xv.y), clamp_id(xv.z), clamp_id(xv.w) };

#if __CUDA_ARCH__ >= 900
    cudaGridDependencySynchronize();               // wait for K1 (bins, rank)
#endif

    // redundant exclusive scan of 3125 bins -> s_offs (identical in all CTAs)
    int c[BPT]; int s = 0;
#pragma unroll
    for (int k = 0; k < BPT; ++k) {
        const int idx = tid * BPT + k;
        c[k] = (idx < NBINS) ? __ldcg(&g_bins[idx]) : 0;   // L2-hot broadcast
        s += c[k];
    }
    int incl = s;
#pragma unroll
    for (int off = 1; off < 32; off <<= 1) {
        int t = __shfl_up_sync(0xffffffff, incl, off);
        if (lane >= off) incl += t;
    }
    if (lane == 31) warp_tot[wid] = incl;
    __syncthreads();
    if (wid == 0 && lane < 8) {                    // scan 8 warp totals
        int wv = warp_tot[lane];
        int wi = wv;
#pragma unroll
        for (int off = 1; off < 8; off <<= 1) {
            int t = __shfl_up_sync(0x000000ff, wi, off);
            if (lane >= off) wi += t;
        }
        warp_tot[lane] = wi - wv;                  // exclusive base per warp
    }
    __syncthreads();
    int base = warp_tot[wid] + (incl - s);
#pragma unroll
    for (int k = 0; k < BPT; ++k) {
        const int idx = tid * BPT + k;
        if (idx < NBINS) s_offs[idx] = base;
        base += c[k];
    }
    __syncthreads();

    // scatter this CTA's 1024 tokens, atomic-free
    const int4 rv = *reinterpret_cast<const int4*>(g_rank + t0);
    const int rk[4] = { rv.x, rv.y, rv.z, rv.w };
#pragma unroll
    for (int k = 0; k < 4; ++k) {
        const int pos = s_offs[v[k] >> 5] + rk[k];
        __stcg(&g_sorted[pos], make_int2(v[k], t0 + k));
    }
}

// ---- K3: gather (PDL consumer) + bins re-zero ----------------------------
__global__ __launch_bounds__(256) void gather_kernel(
    const float* __restrict__ W,
    const float* __restrict__ bias,
    float*       __restrict__ out)
{
    __shared__ __align__(16) float tile[32][TSTR];
    __shared__ int s_id[32], s_tok[32];

    const int tid   = threadIdx.x;
    const int group = blockIdx.x >> 1;
    const int half  = blockIdx.x & 1;
    const int dim0  = half * HDIM;
    const int w = tid >> 5;          // warp -> dims [16w,16w+16) of half
    const int l = tid & 31;          // lane -> sorted token

    // independent: bias load before the dependency sync
    const float4 bv = __ldg(reinterpret_cast<const float4*>(bias) + half * 32 + l);

#if __CUDA_ARCH__ >= 900
    cudaGridDependencySynchronize();               // wait for g_sorted (K2)
#endif

    // restore invariant: first 13 CTAs zero g_bins (after K2's reads, by PDL)
    if (blockIdx.x < (NBINS + 255) / 256) {
        const int idx = blockIdx.x * 256 + tid;
        if (idx < NBINS) __stcg(&g_bins[idx], 0);
    }

    if (tid < 32) {
        int2 p = g_sorted[group * 32 + tid];
        s_id[tid]  = p.x;
        s_tok[tid] = p.y;
    }
    __syncthreads();

    const int vid = s_id[l];
    const float* wp = W + (size_t)(dim0 + w * 16) * VOCAB + (size_t)vid;
    float rr[16];
#pragma unroll
    for (int j = 0; j < 16; ++j)
        rr[j] = __ldg(wp + (size_t)j * VOCAB);     // coalesced via sort

#pragma unroll
    for (int j = 0; j < 4; ++j) {
        float4 v4 = make_float4(rr[4*j], rr[4*j+1], rr[4*j+2], rr[4*j+3]);
        *reinterpret_cast<float4*>(&tile[l][w * 16 + 4 * j]) = v4;
    }
    __syncthreads();

#pragma unroll
    for (int i = 0; i < 4; ++i) {
        const int t    = w * 4 + i;
        const int orig = s_tok[t];
        float4 v4 = *reinterpret_cast<const float4*>(&tile[t][4 * l]);
        v4.x += bv.x; v4.y += bv.y; v4.z += bv.z; v4.w += bv.w;
        __stcs(reinterpret_cast<float4*>(out + (size_t)orig * EMBED + dim0) + l, v4);
    }
}

// ---- host: PDL-chained launches ------------------------------------------
template <typename K, typename... Args>
static void launch_pdl(K kernel, dim3 grid, dim3 block, Args... args)
{
    cudaLaunchAttribute attr;
    attr.id = cudaLaunchAttributeProgrammaticStreamSerialization;
    attr.val.programmaticStreamSerializationAllowed = 1;
    cudaLaunchConfig_t cfg = {};
    cfg.gridDim  = grid;
    cfg.blockDim = block;
    cfg.attrs    = &attr;
    cfg.numAttrs = 1;
    cfg.stream   = 0;
    cudaLaunchKernelEx(&cfg, kernel, args...);
}

extern "C" void kernel_launch(void* const* d_in, const int* in_sizes, int n_in,
                              void* d_out, int out_size)
{
    const int*   x    = (const int*)d_in[0];
    const float* W    = (const float*)d_in[1];
    const float* bias = (const float*)d_in[2];
    float*       out  = (float*)d_out;

    hist_rank_kernel<<<HCTAS, 256>>>(x);
    launch_pdl(scan_scatter_kernel, dim3(HCTAS),           dim3(256), x);
    launch_pdl(gather_kernel,       dim3((NTOK / 32) * 2), dim3(256), W, bias, out);
}